// round 5
// baseline (speedup 1.0000x reference)
#include <cuda_runtime.h>
#include <cuda_fp16.h>
#include <cstdint>

#define EMB   64
#define NMAX  300000
#define EMAX  4200000
#define TB    256

// ---------------- scratch (__device__ globals; allocation-free rule) --------
__device__ int   g_deg  [NMAX];
__device__ float g_dinv [NMAX];
__device__ int   g_loc  [NMAX];
__device__ int   g_bsum [2048];
__device__ int   g_bbase[2048];
__device__ int2  g_rng  [NMAX];               // {row_start, cursor/row_end}
__device__ int   g_adjc [EMAX];               // col index only
__device__ uint2 g_h0[(size_t)NMAX * 16];     // x0 fp16 (4 halves per uint2)
__device__ uint2 g_h1[(size_t)NMAX * 16];     // x1 fp16
__device__ uint2 g_h2[(size_t)NMAX * 16];     // x2 fp16

// ---------------------------------------------------------------------------
__device__ __forceinline__ float4 h4_to_f4(uint2 h) {
    __half2 a = *(__half2*)&h.x;
    __half2 b = *(__half2*)&h.y;
    float2 fa = __half22float2(a), fb = __half22float2(b);
    return make_float4(fa.x, fa.y, fb.x, fb.y);
}
__device__ __forceinline__ uint2 f4_to_h4(float4 v) {
    __half2 a = __floats2half2_rn(v.x, v.y);
    __half2 b = __floats2half2_rn(v.z, v.w);
    uint2 r;
    r.x = *(unsigned*)&a;
    r.y = *(unsigned*)&b;
    return r;
}

// ---------------------------------------------------------------------------
__global__ void k_zero_deg(int n) {
    int i = blockIdx.x * blockDim.x + threadIdx.x;
    if (i < n) g_deg[i] = 0;
}

__global__ void k_count(const int* __restrict__ row, int E) {
    int i = blockIdx.x * blockDim.x + threadIdx.x;
    if (i < E) atomicAdd(&g_deg[row[i]], 1);
}

__global__ void k_scan_local(int n) {
    __shared__ int sh[TB];
    int i = blockIdx.x * TB + threadIdx.x;
    int v = (i < n) ? g_deg[i] : 0;
    sh[threadIdx.x] = v; __syncthreads();
    #pragma unroll
    for (int ofs = 1; ofs < TB; ofs <<= 1) {
        int t = (threadIdx.x >= ofs) ? sh[threadIdx.x - ofs] : 0;
        __syncthreads();
        sh[threadIdx.x] += t;
        __syncthreads();
    }
    if (i < n) g_loc[i] = sh[threadIdx.x] - v;
    if (threadIdx.x == TB - 1) g_bsum[blockIdx.x] = sh[TB - 1];
}

__global__ void k_scan_bsum(int nb) {
    __shared__ int sh[1024];
    int tid = threadIdx.x;
    int c0 = tid * 2, c1 = tid * 2 + 1;
    int a = (c0 < nb) ? g_bsum[c0] : 0;
    int b = (c1 < nb) ? g_bsum[c1] : 0;
    int tot = a + b;
    sh[tid] = tot; __syncthreads();
    #pragma unroll
    for (int ofs = 1; ofs < 1024; ofs <<= 1) {
        int t = (tid >= ofs) ? sh[tid - ofs] : 0;
        __syncthreads();
        sh[tid] += t;
        __syncthreads();
    }
    int base = sh[tid] - tot;
    if (c0 < nb) g_bbase[c0] = base;
    if (c1 < nb) g_bbase[c1] = base + a;
}

__global__ void k_scan_add(int n) {
    int i = blockIdx.x * TB + threadIdx.x;
    if (i >= n) return;
    int o = g_loc[i] + g_bbase[blockIdx.x];
    g_rng[i] = make_int2(o, o);
    g_dinv[i] = rsqrtf((float)(g_deg[i] + 1));   // +1 self loop
}

__global__ void k_fill(const int* __restrict__ row, const int* __restrict__ col, int E) {
    int e = blockIdx.x * blockDim.x + threadIdx.x;
    if (e >= E) return;
    int r = row[e];
    int pos = atomicAdd(&g_rng[r].y, 1);
    g_adjc[pos] = col[e];
}

// emb (fp32) -> x0 (fp16)
__global__ void k_prep(const float* __restrict__ ue,
                       const float* __restrict__ ie,
                       int U, int N) {
    int i = blockIdx.x * blockDim.x + threadIdx.x;   // uint2-chunk id
    int total = N * 16;
    if (i >= total) return;
    int node = i >> 4;
    int c = i & 15;
    const float4* p = (node < U)
        ? (const float4*)ue + (size_t)node * 16
        : (const float4*)ie + (size_t)(node - U) * 16;
    g_h0[i] = f4_to_h4(__ldg(p + c));
}

// ---------------------------------------------------------------------------
// Warp-per-node layer. lane = c (chunk, 0..15) + 16*p (neighbor parity).
// x_new = sum_{nbr} d*dinv[col]*x[col] + d^2*x[node]
// LAST: acc = emb + x1 + x2(self) + x3
template<bool LAST>
__global__ void __launch_bounds__(TB)
k_layer(const uint2* __restrict__ x,
        uint2* __restrict__ xn,
        const float* __restrict__ ue,
        const float* __restrict__ ie,
        int U,
        float* __restrict__ acc,
        int N) {
    int node = (blockIdx.x * blockDim.x + threadIdx.x) >> 5;
    if (node >= N) return;
    int lane = threadIdx.x & 31;
    int c = lane & 15;
    int p = lane >> 4;

    float d = __ldg(&g_dinv[node]);                  // warp-uniform
    int2 rng = __ldg(&g_rng[node]);                  // warp-uniform
    int end = rng.y;

    size_t idx = (size_t)node * 16 + c;
    float4 xs = h4_to_f4(__ldg(x + idx));

    float4 s = make_float4(0.f, 0.f, 0.f, 0.f);

    // each p-half handles every other edge; unroll 2 -> 4 edges in flight/warp
    int e = rng.x + p;
    while (e + 2 < end) {
        int c0 = __ldg(&g_adjc[e]);
        int c1 = __ldg(&g_adjc[e + 2]);
        float4 v0 = h4_to_f4(__ldg(x + (size_t)c0 * 16 + c));
        float4 v1 = h4_to_f4(__ldg(x + (size_t)c1 * 16 + c));
        float w0 = d * __ldg(&g_dinv[c0]);
        float w1 = d * __ldg(&g_dinv[c1]);
        s.x += w0 * v0.x + w1 * v1.x;
        s.y += w0 * v0.y + w1 * v1.y;
        s.z += w0 * v0.z + w1 * v1.z;
        s.w += w0 * v0.w + w1 * v1.w;
        e += 4;
    }
    if (e < end) {
        int c0 = __ldg(&g_adjc[e]);
        float4 v0 = h4_to_f4(__ldg(x + (size_t)c0 * 16 + c));
        float w0 = d * __ldg(&g_dinv[c0]);
        s.x += w0 * v0.x; s.y += w0 * v0.y; s.z += w0 * v0.z; s.w += w0 * v0.w;
    }

    // merge the two parity halves (lane <-> lane^16 hold the same chunk c)
    s.x += __shfl_xor_sync(0xffffffffu, s.x, 16);
    s.y += __shfl_xor_sync(0xffffffffu, s.y, 16);
    s.z += __shfl_xor_sync(0xffffffffu, s.z, 16);
    s.w += __shfl_xor_sync(0xffffffffu, s.w, 16);

    if (p == 0) {
        float sw = d * d;
        s.x += sw * xs.x; s.y += sw * xs.y; s.z += sw * xs.z; s.w += sw * xs.w;

        if (!LAST) {
            xn[idx] = f4_to_h4(s);
        } else {
            const float4* pe = (node < U)
                ? (const float4*)ue + (size_t)node * 16
                : (const float4*)ie + (size_t)(node - U) * 16;
            float4 a  = __ldg(pe + c);
            float4 v1 = h4_to_f4(__ldg(&g_h1[idx]));
            a.x += v1.x + xs.x + s.x;
            a.y += v1.y + xs.y + s.y;
            a.z += v1.z + xs.z + s.z;
            a.w += v1.w + xs.w + s.w;
            ((float4*)acc)[idx] = a;
        }
    }
}

// ---------------------------------------------------------------------------
extern "C" void kernel_launch(void* const* d_in, const int* in_sizes, int n_in,
                              void* d_out, int out_size) {
    const int*   edge = (const int*)d_in[0];
    const float* uemb = (const float*)d_in[1];
    const float* iemb = (const float*)d_in[2];

    int E = in_sizes[0] / 2;
    int U = in_sizes[1] / EMB;
    int I = in_sizes[2] / EMB;
    int N = U + I;

    const int* row = edge;
    const int* col = edge + E;
    float* acc = (float*)d_out;

    uint2* h0; cudaGetSymbolAddress((void**)&h0, g_h0);
    uint2* h1; cudaGetSymbolAddress((void**)&h1, g_h1);
    uint2* h2; cudaGetSymbolAddress((void**)&h2, g_h2);

    int NB = (N + TB - 1) / TB;
    int EB = (E + TB - 1) / TB;

    k_zero_deg  <<<NB, TB>>>(N);
    k_count     <<<EB, TB>>>(row, E);
    k_scan_local<<<NB, TB>>>(N);
    k_scan_bsum <<<1, 1024>>>(NB);
    k_scan_add  <<<NB, TB>>>(N);
    k_fill      <<<EB, TB>>>(row, col, E);

    int pblocks = (N * 16 + TB - 1) / TB;
    k_prep<<<pblocks, TB>>>(uemb, iemb, U, N);

    int lblocks = (N * 32 + TB - 1) / TB;        // warp per node
    k_layer<false><<<lblocks, TB>>>(h0, h1, uemb, iemb, U, acc, N);
    k_layer<false><<<lblocks, TB>>>(h1, h2, uemb, iemb, U, acc, N);
    k_layer<true ><<<lblocks, TB>>>(h2, nullptr, uemb, iemb, U, acc, N);
}

// round 6
// speedup vs baseline: 1.3395x; 1.3395x over previous
#include <cuda_runtime.h>
#include <cuda_fp16.h>
#include <cstdint>

#define EMB   64
#define NMAX  300000
#define EMAX  4200000
#define TB    256

// ---------------- scratch (__device__ globals; allocation-free rule) --------
__device__ int   g_deg  [NMAX];
__device__ float g_dinv [NMAX];
__device__ int   g_loc  [NMAX];
__device__ int   g_bsum [2048];
__device__ int   g_bbase[2048];
__device__ int2  g_rng  [NMAX];               // {row_start, cursor/row_end}
__device__ int   g_adjc [EMAX];               // col index only
__device__ uint2 g_h0[(size_t)NMAX * 16];     // x0 fp16 (4 halves per uint2)
__device__ uint2 g_h1[(size_t)NMAX * 16];     // x1 fp16
__device__ uint2 g_h2[(size_t)NMAX * 16];     // x2 fp16

// ---------------------------------------------------------------------------
__device__ __forceinline__ float4 h4_to_f4(uint2 h) {
    __half2 a = *(__half2*)&h.x;
    __half2 b = *(__half2*)&h.y;
    float2 fa = __half22float2(a), fb = __half22float2(b);
    return make_float4(fa.x, fa.y, fb.x, fb.y);
}
__device__ __forceinline__ uint2 f4_to_h4(float4 v) {
    __half2 a = __floats2half2_rn(v.x, v.y);
    __half2 b = __floats2half2_rn(v.z, v.w);
    uint2 r;
    r.x = *(unsigned*)&a;
    r.y = *(unsigned*)&b;
    return r;
}

// ---------------------------------------------------------------------------
__global__ void k_zero_deg(int n) {
    int i = blockIdx.x * blockDim.x + threadIdx.x;
    if (i < n) g_deg[i] = 0;
}

__global__ void k_count(const int* __restrict__ row, int E) {
    int i = blockIdx.x * blockDim.x + threadIdx.x;
    if (i < E) atomicAdd(&g_deg[row[i]], 1);
}

__global__ void k_scan_local(int n) {
    __shared__ int sh[TB];
    int i = blockIdx.x * TB + threadIdx.x;
    int v = (i < n) ? g_deg[i] : 0;
    sh[threadIdx.x] = v; __syncthreads();
    #pragma unroll
    for (int ofs = 1; ofs < TB; ofs <<= 1) {
        int t = (threadIdx.x >= ofs) ? sh[threadIdx.x - ofs] : 0;
        __syncthreads();
        sh[threadIdx.x] += t;
        __syncthreads();
    }
    if (i < n) g_loc[i] = sh[threadIdx.x] - v;
    if (threadIdx.x == TB - 1) g_bsum[blockIdx.x] = sh[TB - 1];
}

__global__ void k_scan_bsum(int nb) {
    __shared__ int sh[1024];
    int tid = threadIdx.x;
    int c0 = tid * 2, c1 = tid * 2 + 1;
    int a = (c0 < nb) ? g_bsum[c0] : 0;
    int b = (c1 < nb) ? g_bsum[c1] : 0;
    int tot = a + b;
    sh[tid] = tot; __syncthreads();
    #pragma unroll
    for (int ofs = 1; ofs < 1024; ofs <<= 1) {
        int t = (tid >= ofs) ? sh[tid - ofs] : 0;
        __syncthreads();
        sh[tid] += t;
        __syncthreads();
    }
    int base = sh[tid] - tot;
    if (c0 < nb) g_bbase[c0] = base;
    if (c1 < nb) g_bbase[c1] = base + a;
}

__global__ void k_scan_add(int n) {
    int i = blockIdx.x * TB + threadIdx.x;
    if (i >= n) return;
    int o = g_loc[i] + g_bbase[blockIdx.x];
    g_rng[i] = make_int2(o, o);
    g_dinv[i] = rsqrtf((float)(g_deg[i] + 1));   // +1 self loop
}

__global__ void k_fill(const int* __restrict__ row, const int* __restrict__ col, int E) {
    int e = blockIdx.x * blockDim.x + threadIdx.x;
    if (e >= E) return;
    int r = row[e];
    int pos = atomicAdd(&g_rng[r].y, 1);
    g_adjc[pos] = col[e];
}

// emb (fp32) -> x0 (fp16)
__global__ void k_prep(const float* __restrict__ ue,
                       const float* __restrict__ ie,
                       int U, int N) {
    int i = blockIdx.x * blockDim.x + threadIdx.x;   // uint2-chunk id
    int total = N * 16;
    if (i >= total) return;
    int node = i >> 4;
    int c = i & 15;
    const float4* p = (node < U)
        ? (const float4*)ue + (size_t)node * 16
        : (const float4*)ie + (size_t)(node - U) * 16;
    g_h0[i] = f4_to_h4(__ldg(p + c));
}

// ---------------------------------------------------------------------------
// Fused layer: 16 threads per node (half-warp), thread c owns halves [4c,4c+4).
// x_new = sum_{nbr} d*dinv[col]*x[col] + d^2*x[node]
// LAST: acc = emb + x1 + x2(self) + x3
template<bool LAST>
__global__ void __launch_bounds__(TB)
k_layer(const uint2* __restrict__ x,
        uint2* __restrict__ xn,
        const float* __restrict__ ue,
        const float* __restrict__ ie,
        int U,
        float* __restrict__ acc,
        int N) {
    int t = blockIdx.x * blockDim.x + threadIdx.x;
    int node = t >> 4;
    if (node >= N) return;
    int c = t & 15;

    float d = __ldg(&g_dinv[node]);
    int2 rng = __ldg(&g_rng[node]);
    int e = rng.x, end = rng.y;

    size_t idx = (size_t)node * 16 + c;
    float4 xs = h4_to_f4(__ldg(x + idx));
    float sw = d * d;
    float4 s0 = make_float4(sw * xs.x, sw * xs.y, sw * xs.z, sw * xs.w);
    float4 s1 = make_float4(0.f, 0.f, 0.f, 0.f);

    // 4-wide unroll: 4 adj + 4 gathers + 4 dinv in flight, 2 accumulator chains
    while (e + 4 <= end) {
        int c0 = __ldg(&g_adjc[e]);
        int c1 = __ldg(&g_adjc[e + 1]);
        int c2 = __ldg(&g_adjc[e + 2]);
        int c3 = __ldg(&g_adjc[e + 3]);
        float4 v0 = h4_to_f4(__ldg(x + (size_t)c0 * 16 + c));
        float4 v1 = h4_to_f4(__ldg(x + (size_t)c1 * 16 + c));
        float4 v2 = h4_to_f4(__ldg(x + (size_t)c2 * 16 + c));
        float4 v3 = h4_to_f4(__ldg(x + (size_t)c3 * 16 + c));
        float w0 = d * __ldg(&g_dinv[c0]);
        float w1 = d * __ldg(&g_dinv[c1]);
        float w2 = d * __ldg(&g_dinv[c2]);
        float w3 = d * __ldg(&g_dinv[c3]);
        s0.x += w0 * v0.x + w2 * v2.x;  s1.x += w1 * v1.x + w3 * v3.x;
        s0.y += w0 * v0.y + w2 * v2.y;  s1.y += w1 * v1.y + w3 * v3.y;
        s0.z += w0 * v0.z + w2 * v2.z;  s1.z += w1 * v1.z + w3 * v3.z;
        s0.w += w0 * v0.w + w2 * v2.w;  s1.w += w1 * v1.w + w3 * v3.w;
        e += 4;
    }
    if (e + 2 <= end) {
        int c0 = __ldg(&g_adjc[e]);
        int c1 = __ldg(&g_adjc[e + 1]);
        float4 v0 = h4_to_f4(__ldg(x + (size_t)c0 * 16 + c));
        float4 v1 = h4_to_f4(__ldg(x + (size_t)c1 * 16 + c));
        float w0 = d * __ldg(&g_dinv[c0]);
        float w1 = d * __ldg(&g_dinv[c1]);
        s0.x += w0 * v0.x; s0.y += w0 * v0.y; s0.z += w0 * v0.z; s0.w += w0 * v0.w;
        s1.x += w1 * v1.x; s1.y += w1 * v1.y; s1.z += w1 * v1.z; s1.w += w1 * v1.w;
        e += 2;
    }
    if (e < end) {
        int c0 = __ldg(&g_adjc[e]);
        float4 v0 = h4_to_f4(__ldg(x + (size_t)c0 * 16 + c));
        float w0 = d * __ldg(&g_dinv[c0]);
        s0.x += w0 * v0.x; s0.y += w0 * v0.y; s0.z += w0 * v0.z; s0.w += w0 * v0.w;
    }
    float4 s = make_float4(s0.x + s1.x, s0.y + s1.y, s0.z + s1.z, s0.w + s1.w);

    if (!LAST) {
        xn[idx] = f4_to_h4(s);
    } else {
        const float4* pe = (node < U)
            ? (const float4*)ue + (size_t)node * 16
            : (const float4*)ie + (size_t)(node - U) * 16;
        float4 a  = __ldg(pe + c);
        float4 v1 = h4_to_f4(__ldg(&g_h1[idx]));
        a.x += v1.x + xs.x + s.x;
        a.y += v1.y + xs.y + s.y;
        a.z += v1.z + xs.z + s.z;
        a.w += v1.w + xs.w + s.w;
        ((float4*)acc)[idx] = a;
    }
}

// ---------------------------------------------------------------------------
extern "C" void kernel_launch(void* const* d_in, const int* in_sizes, int n_in,
                              void* d_out, int out_size) {
    const int*   edge = (const int*)d_in[0];
    const float* uemb = (const float*)d_in[1];
    const float* iemb = (const float*)d_in[2];

    int E = in_sizes[0] / 2;
    int U = in_sizes[1] / EMB;
    int I = in_sizes[2] / EMB;
    int N = U + I;

    const int* row = edge;
    const int* col = edge + E;
    float* acc = (float*)d_out;

    uint2* h0; cudaGetSymbolAddress((void**)&h0, g_h0);
    uint2* h1; cudaGetSymbolAddress((void**)&h1, g_h1);
    uint2* h2; cudaGetSymbolAddress((void**)&h2, g_h2);

    int NB = (N + TB - 1) / TB;
    int EB = (E + TB - 1) / TB;

    k_zero_deg  <<<NB, TB>>>(N);
    k_count     <<<EB, TB>>>(row, E);
    k_scan_local<<<NB, TB>>>(N);
    k_scan_bsum <<<1, 1024>>>(NB);
    k_scan_add  <<<NB, TB>>>(N);
    k_fill      <<<EB, TB>>>(row, col, E);

    int pblocks = (N * 16 + TB - 1) / TB;
    k_prep<<<pblocks, TB>>>(uemb, iemb, U, N);

    int lblocks = (N * 16 + TB - 1) / TB;        // half-warp per node
    k_layer<false><<<lblocks, TB>>>(h0, h1, uemb, iemb, U, acc, N);
    k_layer<false><<<lblocks, TB>>>(h1, h2, uemb, iemb, U, acc, N);
    k_layer<true ><<<lblocks, TB>>>(h2, nullptr, uemb, iemb, U, acc, N);
}

// round 7
// speedup vs baseline: 1.3498x; 1.0077x over previous
#include <cuda_runtime.h>
#include <cuda_fp16.h>
#include <cstdint>

#define EMB   64
#define NMAX  300000
#define EMAX  4200000
#define TB    256

// ---------------- scratch (__device__ globals; allocation-free rule) --------
__device__ int   g_deg  [NMAX];
__device__ float g_dinv [NMAX];
__device__ int   g_loc  [NMAX];
__device__ int   g_bsum [2048];
__device__ int   g_bbase[2048];
__device__ int2  g_rng  [NMAX];               // {row_start, cursor/row_end}
__device__ int2  g_adj  [EMAX];               // {col, bits(dinv[col])}
__device__ uint2 g_h0[(size_t)NMAX * 16];     // x0 fp16 (4 halves per uint2)
__device__ uint2 g_h1[(size_t)NMAX * 16];     // x1 fp16
__device__ uint2 g_h2[(size_t)NMAX * 16];     // x2 fp16

// ---------------------------------------------------------------------------
__device__ __forceinline__ float4 h4_to_f4(uint2 h) {
    __half2 a = *(__half2*)&h.x;
    __half2 b = *(__half2*)&h.y;
    float2 fa = __half22float2(a), fb = __half22float2(b);
    return make_float4(fa.x, fa.y, fb.x, fb.y);
}
__device__ __forceinline__ uint2 f4_to_h4(float4 v) {
    __half2 a = __floats2half2_rn(v.x, v.y);
    __half2 b = __floats2half2_rn(v.z, v.w);
    uint2 r;
    r.x = *(unsigned*)&a;
    r.y = *(unsigned*)&b;
    return r;
}

// ---------------------------------------------------------------------------
__global__ void k_zero_deg(int n) {
    int i = blockIdx.x * blockDim.x + threadIdx.x;
    if (i < n) g_deg[i] = 0;
}

// mirrored halves: each interaction (u,v) contributes deg[u]++ and deg[v]++
__global__ void k_count_sym(const int* __restrict__ row,
                            const int* __restrict__ col, int Eh) {
    int i = blockIdx.x * blockDim.x + threadIdx.x;
    if (i >= Eh) return;
    atomicAdd(&g_deg[row[i]], 1);
    atomicAdd(&g_deg[col[i]], 1);
}

__global__ void k_scan_local(int n) {
    __shared__ int sh[TB];
    int i = blockIdx.x * TB + threadIdx.x;
    int v = (i < n) ? g_deg[i] : 0;
    sh[threadIdx.x] = v; __syncthreads();
    #pragma unroll
    for (int ofs = 1; ofs < TB; ofs <<= 1) {
        int t = (threadIdx.x >= ofs) ? sh[threadIdx.x - ofs] : 0;
        __syncthreads();
        sh[threadIdx.x] += t;
        __syncthreads();
    }
    if (i < n) g_loc[i] = sh[threadIdx.x] - v;
    if (threadIdx.x == TB - 1) g_bsum[blockIdx.x] = sh[TB - 1];
}

__global__ void k_scan_bsum(int nb) {
    __shared__ int sh[1024];
    int tid = threadIdx.x;
    int c0 = tid * 2, c1 = tid * 2 + 1;
    int a = (c0 < nb) ? g_bsum[c0] : 0;
    int b = (c1 < nb) ? g_bsum[c1] : 0;
    int tot = a + b;
    sh[tid] = tot; __syncthreads();
    #pragma unroll
    for (int ofs = 1; ofs < 1024; ofs <<= 1) {
        int t = (tid >= ofs) ? sh[tid - ofs] : 0;
        __syncthreads();
        sh[tid] += t;
        __syncthreads();
    }
    int base = sh[tid] - tot;
    if (c0 < nb) g_bbase[c0] = base;
    if (c1 < nb) g_bbase[c1] = base + a;
}

__global__ void k_scan_add(int n) {
    int i = blockIdx.x * TB + threadIdx.x;
    if (i >= n) return;
    int o = g_loc[i] + g_bbase[blockIdx.x];
    g_rng[i] = make_int2(o, o);
    g_dinv[i] = rsqrtf((float)(g_deg[i] + 1));   // +1 self loop
}

// fill both directions from the interaction half
__global__ void k_fill_sym(const int* __restrict__ row,
                           const int* __restrict__ col, int Eh) {
    int i = blockIdx.x * blockDim.x + threadIdx.x;
    if (i >= Eh) return;
    int u = row[i];
    int v = col[i];
    float du = __ldg(&g_dinv[u]);
    float dv = __ldg(&g_dinv[v]);
    int pu = atomicAdd(&g_rng[u].y, 1);
    g_adj[pu] = make_int2(v, __float_as_int(dv));
    int pv = atomicAdd(&g_rng[v].y, 1);
    g_adj[pv] = make_int2(u, __float_as_int(du));
}

// emb (fp32) -> x0 (fp16)
__global__ void k_prep(const float* __restrict__ ue,
                       const float* __restrict__ ie,
                       int U, int N) {
    int i = blockIdx.x * blockDim.x + threadIdx.x;   // uint2-chunk id
    int total = N * 16;
    if (i >= total) return;
    int node = i >> 4;
    int c = i & 15;
    const float4* p = (node < U)
        ? (const float4*)ue + (size_t)node * 16
        : (const float4*)ie + (size_t)(node - U) * 16;
    g_h0[i] = f4_to_h4(__ldg(p + c));
}

// ---------------------------------------------------------------------------
// Fused layer: 16 threads per node (half-warp), thread c owns halves [4c,4c+4).
// x_new = sum_{nbr} d*dinv[col]*x[col] + d^2*x[node]
// LAST: acc = emb + x1 + x2(self) + x3
template<bool LAST>
__global__ void __launch_bounds__(TB)
k_layer(const uint2* __restrict__ x,
        uint2* __restrict__ xn,
        const float* __restrict__ ue,
        const float* __restrict__ ie,
        int U,
        float* __restrict__ acc,
        int N) {
    int t = blockIdx.x * blockDim.x + threadIdx.x;
    int node = t >> 4;
    if (node >= N) return;
    int c = t & 15;

    float d = __ldg(&g_dinv[node]);
    int2 rng = __ldg(&g_rng[node]);
    int e = rng.x, end = rng.y;

    size_t idx = (size_t)node * 16 + c;
    float4 xs = h4_to_f4(__ldg(x + idx));
    float sw = d * d;
    float4 s0 = make_float4(sw * xs.x, sw * xs.y, sw * xs.z, sw * xs.w);
    float4 s1 = make_float4(0.f, 0.f, 0.f, 0.f);

    // 4-wide unroll: 4 adj(int2) + 4 row gathers in flight, 2 accumulators
    while (e + 4 <= end) {
        int2 a0 = __ldg(&g_adj[e]);
        int2 a1 = __ldg(&g_adj[e + 1]);
        int2 a2 = __ldg(&g_adj[e + 2]);
        int2 a3 = __ldg(&g_adj[e + 3]);
        float4 v0 = h4_to_f4(__ldg(x + (size_t)a0.x * 16 + c));
        float4 v1 = h4_to_f4(__ldg(x + (size_t)a1.x * 16 + c));
        float4 v2 = h4_to_f4(__ldg(x + (size_t)a2.x * 16 + c));
        float4 v3 = h4_to_f4(__ldg(x + (size_t)a3.x * 16 + c));
        float w0 = d * __int_as_float(a0.y);
        float w1 = d * __int_as_float(a1.y);
        float w2 = d * __int_as_float(a2.y);
        float w3 = d * __int_as_float(a3.y);
        s0.x += w0 * v0.x + w2 * v2.x;  s1.x += w1 * v1.x + w3 * v3.x;
        s0.y += w0 * v0.y + w2 * v2.y;  s1.y += w1 * v1.y + w3 * v3.y;
        s0.z += w0 * v0.z + w2 * v2.z;  s1.z += w1 * v1.z + w3 * v3.z;
        s0.w += w0 * v0.w + w2 * v2.w;  s1.w += w1 * v1.w + w3 * v3.w;
        e += 4;
    }
    if (e + 2 <= end) {
        int2 a0 = __ldg(&g_adj[e]);
        int2 a1 = __ldg(&g_adj[e + 1]);
        float4 v0 = h4_to_f4(__ldg(x + (size_t)a0.x * 16 + c));
        float4 v1 = h4_to_f4(__ldg(x + (size_t)a1.x * 16 + c));
        float w0 = d * __int_as_float(a0.y);
        float w1 = d * __int_as_float(a1.y);
        s0.x += w0 * v0.x; s0.y += w0 * v0.y; s0.z += w0 * v0.z; s0.w += w0 * v0.w;
        s1.x += w1 * v1.x; s1.y += w1 * v1.y; s1.z += w1 * v1.z; s1.w += w1 * v1.w;
        e += 2;
    }
    if (e < end) {
        int2 a0 = __ldg(&g_adj[e]);
        float4 v0 = h4_to_f4(__ldg(x + (size_t)a0.x * 16 + c));
        float w0 = d * __int_as_float(a0.y);
        s0.x += w0 * v0.x; s0.y += w0 * v0.y; s0.z += w0 * v0.z; s0.w += w0 * v0.w;
    }
    float4 s = make_float4(s0.x + s1.x, s0.y + s1.y, s0.z + s1.z, s0.w + s1.w);

    if (!LAST) {
        xn[idx] = f4_to_h4(s);
    } else {
        const float4* pe = (node < U)
            ? (const float4*)ue + (size_t)node * 16
            : (const float4*)ie + (size_t)(node - U) * 16;
        float4 a  = __ldg(pe + c);
        float4 v1 = h4_to_f4(__ldg(&g_h1[idx]));
        a.x += v1.x + xs.x + s.x;
        a.y += v1.y + xs.y + s.y;
        a.z += v1.z + xs.z + s.z;
        a.w += v1.w + xs.w + s.w;
        ((float4*)acc)[idx] = a;
    }
}

// ---------------------------------------------------------------------------
extern "C" void kernel_launch(void* const* d_in, const int* in_sizes, int n_in,
                              void* d_out, int out_size) {
    const int*   edge = (const int*)d_in[0];
    const float* uemb = (const float*)d_in[1];
    const float* iemb = (const float*)d_in[2];

    int E = in_sizes[0] / 2;       // total directed edges
    int Eh = E / 2;                // unique interactions (mirrored halves)
    int U = in_sizes[1] / EMB;
    int I = in_sizes[2] / EMB;
    int N = U + I;

    const int* row = edge;         // first Eh entries: users
    const int* col = edge + E;     // first Eh entries: items
    float* acc = (float*)d_out;

    uint2* h0; cudaGetSymbolAddress((void**)&h0, g_h0);
    uint2* h1; cudaGetSymbolAddress((void**)&h1, g_h1);
    uint2* h2; cudaGetSymbolAddress((void**)&h2, g_h2);

    int NB = (N + TB - 1) / TB;
    int EBh = (Eh + TB - 1) / TB;

    k_zero_deg  <<<NB, TB>>>(N);
    k_count_sym <<<EBh, TB>>>(row, col, Eh);
    k_scan_local<<<NB, TB>>>(N);
    k_scan_bsum <<<1, 1024>>>(NB);
    k_scan_add  <<<NB, TB>>>(N);
    k_fill_sym  <<<EBh, TB>>>(row, col, Eh);

    int pblocks = (N * 16 + TB - 1) / TB;
    k_prep<<<pblocks, TB>>>(uemb, iemb, U, N);

    int lblocks = (N * 16 + TB - 1) / TB;        // half-warp per node
    k_layer<false><<<lblocks, TB>>>(h0, h1, uemb, iemb, U, acc, N);
    k_layer<false><<<lblocks, TB>>>(h1, h2, uemb, iemb, U, acc, N);
    k_layer<true ><<<lblocks, TB>>>(h2, nullptr, uemb, iemb, U, acc, N);
}